// round 1
// baseline (speedup 1.0000x reference)
#include <cuda_runtime.h>
#include <cstdint>

// Reference collapses exactly: xf == 0, so only corner 0 (all-floor) has
// nonzero weight (== 1). out[n] = embedding[hash(trunc(x[n]*128))].
// hash = (u0*1 ^ u1*2654435761 ^ u2*805459861) & (2^19 - 1)

static constexpr unsigned P1 = 2654435761u;
static constexpr unsigned P2 = 805459861u;
static constexpr unsigned HASH_MASK = 524288u - 1u;  // 2^19

__global__ void __launch_bounds__(256)
hashgrid_gather_kernel(const float* __restrict__ x,
                       const float4* __restrict__ emb,  // [HASHMAP_SIZE][2] float4
                       float4* __restrict__ out,        // [N][2] float4
                       int n)
{
    int i = blockIdx.x * blockDim.x + threadIdx.x;
    if (i >= n) return;

    // x in [0,1): trunc(x*128) matches astype(int32) (toward-zero, nonneg)
    float x0 = x[3 * i + 0];
    float x1 = x[3 * i + 1];
    float x2 = x[3 * i + 2];

    unsigned u0 = (unsigned)__float2int_rz(x0 * 128.0f);
    unsigned u1 = (unsigned)__float2int_rz(x1 * 128.0f);
    unsigned u2 = (unsigned)__float2int_rz(x2 * 128.0f);

    unsigned h = (u0 ^ (u1 * P1) ^ (u2 * P2)) & HASH_MASK;

    // 32-byte embedding row: two float4 loads (L2-resident table, 16 MB)
    float4 a = __ldg(&emb[2 * h + 0]);
    float4 b = __ldg(&emb[2 * h + 1]);

    out[2 * i + 0] = a;
    out[2 * i + 1] = b;
}

extern "C" void kernel_launch(void* const* d_in, const int* in_sizes, int n_in,
                              void* d_out, int out_size)
{
    const float*  x   = (const float*)d_in[0];
    const float4* emb = (const float4*)d_in[1];
    float4*       out = (float4*)d_out;

    int n = in_sizes[0] / 3;  // N_POINTS
    int threads = 256;
    int blocks = (n + threads - 1) / threads;
    hashgrid_gather_kernel<<<blocks, threads>>>(x, emb, out, n);
}

// round 2
// speedup vs baseline: 1.1719x; 1.1719x over previous
#include <cuda_runtime.h>
#include <cstdint>

// Reference collapses exactly: xf == 0, so only corner 0 (all-floor) has
// weight 1. out[n] = embedding[hash(trunc(x[n]*128))].
// hash = (u0 ^ u1*2654435761 ^ u2*805459861) & (2^19 - 1)
//
// R2: 2 threads per point. The lane pair loads the two 16B halves of the
// same random 32B embedding row in ONE warp instruction -> one L1 wavefront
// per point (was two). Stores stay fully coalesced (pair writes adjacent
// float4 of out).

static constexpr unsigned P1 = 2654435761u;
static constexpr unsigned P2 = 805459861u;
static constexpr unsigned HASH_MASK = 524288u - 1u;  // 2^19

__global__ void __launch_bounds__(256)
hashgrid_gather_pair_kernel(const float* __restrict__ x,
                            const float4* __restrict__ emb,  // [H][2] float4
                            float4* __restrict__ out,        // [N][2] float4
                            int n)
{
    int t = blockIdx.x * blockDim.x + threadIdx.x;
    int p    = t >> 1;   // point index (lane pair shares a point)
    int half = t & 1;    // which 16B half of the 32B row
    if (p >= n) return;

    // Both lanes of the pair load the same 3 floats (broadcast within line).
    float x0 = x[3 * p + 0];
    float x1 = x[3 * p + 1];
    float x2 = x[3 * p + 2];

    unsigned u0 = (unsigned)__float2int_rz(x0 * 128.0f);
    unsigned u1 = (unsigned)__float2int_rz(x1 * 128.0f);
    unsigned u2 = (unsigned)__float2int_rz(x2 * 128.0f);

    unsigned h = (u0 ^ (u1 * P1) ^ (u2 * P2)) & HASH_MASK;

    // Pair's two 16B loads hit the same 128B line -> 1 L1 wavefront/point.
    float4 v = __ldg(&emb[2 * h + half]);

    out[2 * p + half] = v;
}

extern "C" void kernel_launch(void* const* d_in, const int* in_sizes, int n_in,
                              void* d_out, int out_size)
{
    const float*  x   = (const float*)d_in[0];
    const float4* emb = (const float4*)d_in[1];
    float4*       out = (float4*)d_out;

    int n = in_sizes[0] / 3;          // N_POINTS
    long long threads_total = 2LL * n;
    int threads = 256;
    int blocks = (int)((threads_total + threads - 1) / threads);
    hashgrid_gather_pair_kernel<<<blocks, threads>>>(x, emb, out, n);
}

// round 3
// speedup vs baseline: 1.2581x; 1.0735x over previous
#include <cuda_runtime.h>
#include <cstdint>

// out[n] = embedding[hash(trunc(x[n]*128))]  (reference's xf==0 collapses the
// trilerp to corner 0 with weight 1; bit-exact).
// hash = (u0 ^ u1*2654435761 ^ u2*805459861) & (2^19 - 1)
//
// R3: latency-bound fix. 2 threads per point (pair loads the two 16B halves
// of one random 32B row in one warp instruction -> 1 L1 wavefront/point),
// and each thread handles 4 points with front-batched independent loads
// (MLP=4). Points are strided by 16 inside the warp's 64-point tile so each
// store instruction writes 512 contiguous bytes.

static constexpr unsigned P1 = 2654435761u;
static constexpr unsigned P2 = 805459861u;
static constexpr unsigned HASH_MASK = 524288u - 1u;  // 2^19
static constexpr int PTS_PER_THREAD = 4;
static constexpr int THREADS = 256;
static constexpr int PTS_PER_BLOCK = THREADS / 2 * PTS_PER_THREAD;  // 512

__global__ void __launch_bounds__(THREADS)
hashgrid_gather_ilp4_kernel(const float* __restrict__ x,
                            const float4* __restrict__ emb,  // [H][2] float4
                            float4* __restrict__ out,        // [N][2] float4
                            int n)
{
    int tid  = threadIdx.x;
    int w    = tid >> 5;          // warp index in block
    int lane = tid & 31;
    int qw   = lane >> 1;         // pair index within warp: 0..15
    int half = lane & 1;          // which 16B half of the 32B row

    // Warp owns 64 consecutive points; iteration k handles base + 16k.
    int base = blockIdx.x * PTS_PER_BLOCK + w * 64 + qw;

    float xv[PTS_PER_THREAD][3];
#pragma unroll
    for (int k = 0; k < PTS_PER_THREAD; k++) {
        int p = base + 16 * k;
        if (p < n) {
            xv[k][0] = x[3 * p + 0];
            xv[k][1] = x[3 * p + 1];
            xv[k][2] = x[3 * p + 2];
        }
    }

    unsigned h[PTS_PER_THREAD];
#pragma unroll
    for (int k = 0; k < PTS_PER_THREAD; k++) {
        unsigned u0 = (unsigned)__float2int_rz(xv[k][0] * 128.0f);
        unsigned u1 = (unsigned)__float2int_rz(xv[k][1] * 128.0f);
        unsigned u2 = (unsigned)__float2int_rz(xv[k][2] * 128.0f);
        h[k] = (u0 ^ (u1 * P1) ^ (u2 * P2)) & HASH_MASK;
    }

    float4 v[PTS_PER_THREAD];
#pragma unroll
    for (int k = 0; k < PTS_PER_THREAD; k++) {
        if (base + 16 * k < n)
            v[k] = __ldg(&emb[2 * h[k] + half]);
    }

#pragma unroll
    for (int k = 0; k < PTS_PER_THREAD; k++) {
        int p = base + 16 * k;
        if (p < n)
            out[2 * p + half] = v[k];
    }
}

extern "C" void kernel_launch(void* const* d_in, const int* in_sizes, int n_in,
                              void* d_out, int out_size)
{
    const float*  x   = (const float*)d_in[0];
    const float4* emb = (const float4*)d_in[1];
    float4*       out = (float4*)d_out;

    int n = in_sizes[0] / 3;  // N_POINTS
    int blocks = (n + PTS_PER_BLOCK - 1) / PTS_PER_BLOCK;
    hashgrid_gather_ilp4_kernel<<<blocks, THREADS>>>(x, emb, out, n);
}